// round 1
// baseline (speedup 1.0000x reference)
#include <cuda_runtime.h>
#include <cuda_bf16.h>
#include <math.h>

// ---------------------------------------------------------------------------
// LayerNorm LSTM cell, B=4096, I=H=1024.
//   i2h = inputs @ w_i2h^T + b_i2h        [B, 4H]
//   h2h = hx     @ w_h2h^T + b_h2h        [B, 4H]
//   x   = LN(i2h) + LN(h2h)               (per-row LN over 4H, unbiased std)
//   gates -> cx_new -> LN(cx_new) -> hx_new
// Output: hx_new [B,H] followed by cx_new [B,H].
// ---------------------------------------------------------------------------

#define B_DIM   4096
#define H_DIM   1024
#define FH_DIM  4096      // 4*H
#define K_DIM   1024
#define LN_EPS  1e-5f
#define FGBIAS  (-1.0f)

// Scratch for the two GEMM outputs (allocation-free rule: device globals).
__device__ float g_i2h[(size_t)B_DIM * FH_DIM];
__device__ float g_h2h[(size_t)B_DIM * FH_DIM];

// ------------------------------ GEMM (NT) ---------------------------------
// C[m,n] = sum_k A[m,k] * W[n,k] + bias[n]
// A: [M,K] row-major, W: [N,K] row-major. M=N=4096, K=1024 (all multiples of tiles).
#define BM 128
#define BN 128
#define BK 16
#define TM 8
#define TN 8

__global__ __launch_bounds__(256, 2)
void gemm_nt_bias(const float* __restrict__ A,
                  const float* __restrict__ W,
                  const float* __restrict__ bias,
                  int which,          // 0 -> g_i2h, 1 -> g_h2h
                  int M, int N, int K)
{
    float* __restrict__ C = which ? g_h2h : g_i2h;

    __shared__ float As[BK][BM + 4];
    __shared__ float Ws[BK][BN + 4];

    const int bm = blockIdx.y * BM;
    const int bn = blockIdx.x * BN;
    const int tid = threadIdx.x;
    const int tx = tid & 15;          // 16 thread cols
    const int ty = tid >> 4;          // 16 thread rows

    float acc[TM][TN];
#pragma unroll
    for (int i = 0; i < TM; i++)
#pragma unroll
        for (int j = 0; j < TN; j++) acc[i][j] = 0.f;

    for (int k0 = 0; k0 < K; k0 += BK) {
        // Load tiles: 128 rows x 16 k-cols each = 512 float4 per operand.
#pragma unroll
        for (int it = 0; it < 2; it++) {
            int idx = tid + it * 256;          // float4 index 0..511
            int row = idx >> 2;                // 0..127
            int kk  = (idx & 3) << 2;          // 0,4,8,12
            float4 va = *reinterpret_cast<const float4*>(
                &A[(size_t)(bm + row) * K + k0 + kk]);
            As[kk + 0][row] = va.x; As[kk + 1][row] = va.y;
            As[kk + 2][row] = va.z; As[kk + 3][row] = va.w;
            float4 vw = *reinterpret_cast<const float4*>(
                &W[(size_t)(bn + row) * K + k0 + kk]);
            Ws[kk + 0][row] = vw.x; Ws[kk + 1][row] = vw.y;
            Ws[kk + 2][row] = vw.z; Ws[kk + 3][row] = vw.w;
        }
        __syncthreads();

#pragma unroll
        for (int kk = 0; kk < BK; kk++) {
            float a[TM], w[TN];
            // vectorized smem reads (rows padded by 4 floats, still 16B aligned)
            *reinterpret_cast<float4*>(&a[0]) =
                *reinterpret_cast<const float4*>(&As[kk][ty * TM + 0]);
            *reinterpret_cast<float4*>(&a[4]) =
                *reinterpret_cast<const float4*>(&As[kk][ty * TM + 4]);
            *reinterpret_cast<float4*>(&w[0]) =
                *reinterpret_cast<const float4*>(&Ws[kk][tx * TN + 0]);
            *reinterpret_cast<float4*>(&w[4]) =
                *reinterpret_cast<const float4*>(&Ws[kk][tx * TN + 4]);
#pragma unroll
            for (int i = 0; i < TM; i++)
#pragma unroll
                for (int j = 0; j < TN; j++)
                    acc[i][j] = fmaf(a[i], w[j], acc[i][j]);
        }
        __syncthreads();
    }

    // Epilogue: add bias, store.
#pragma unroll
    for (int i = 0; i < TM; i++) {
        const int m = bm + ty * TM + i;
#pragma unroll
        for (int j = 0; j < TN; j += 4) {
            const int n = bn + tx * TN + j;
            float4 v;
            v.x = acc[i][j + 0] + bias[n + 0];
            v.y = acc[i][j + 1] + bias[n + 1];
            v.z = acc[i][j + 2] + bias[n + 2];
            v.w = acc[i][j + 3] + bias[n + 3];
            *reinterpret_cast<float4*>(&C[(size_t)m * N + n]) = v;
        }
    }
}

// --------------------------- fused LN/gate epilogue ------------------------
__device__ __forceinline__ float warp_sum(float v) {
#pragma unroll
    for (int o = 16; o; o >>= 1) v += __shfl_down_sync(0xffffffffu, v, o);
    return v;
}

__device__ __forceinline__ float sigmoidf_(float x) {
    return 1.0f / (1.0f + expf(-x));
}

__global__ __launch_bounds__(256)
void lstm_epilogue(const float* __restrict__ cx,
                   const float* __restrict__ w1, const float* __restrict__ b1,  // ln_i2h
                   const float* __restrict__ w2, const float* __restrict__ b2,  // ln_h2h
                   const float* __restrict__ w3, const float* __restrict__ b3,  // ln_h2o
                   float* __restrict__ hx_new,
                   float* __restrict__ cx_new)
{
    const int r   = blockIdx.x;          // batch row
    const int tid = threadIdx.x;
    const int lane = tid & 31;
    const int wrp  = tid >> 5;

    const float* __restrict__ ri = g_i2h + (size_t)r * FH_DIM;
    const float* __restrict__ rh = g_h2h + (size_t)r * FH_DIM;

    __shared__ float s_i[FH_DIM];
    __shared__ float s_h[FH_DIM];
    __shared__ float sc[4][8];

    // Pass 1: stage rows in smem + accumulate sum / sumsq for both LNs.
    float s1 = 0.f, q1 = 0.f, s2 = 0.f, q2 = 0.f;
    for (int j = tid; j < FH_DIM; j += 256) {
        float a = ri[j], b = rh[j];
        s_i[j] = a; s_h[j] = b;
        s1 += a; q1 += a * a;
        s2 += b; q2 += b * b;
    }
    s1 = warp_sum(s1); q1 = warp_sum(q1);
    s2 = warp_sum(s2); q2 = warp_sum(q2);
    if (lane == 0) { sc[0][wrp] = s1; sc[1][wrp] = q1; sc[2][wrp] = s2; sc[3][wrp] = q2; }
    __syncthreads();
    if (tid == 0) {
        float t0 = 0, t1 = 0, t2 = 0, t3 = 0;
#pragma unroll
        for (int i = 0; i < 8; i++) { t0 += sc[0][i]; t1 += sc[1][i]; t2 += sc[2][i]; t3 += sc[3][i]; }
        sc[0][0] = t0; sc[1][0] = t1; sc[2][0] = t2; sc[3][0] = t3;
    }
    __syncthreads();
    s1 = sc[0][0]; q1 = sc[1][0]; s2 = sc[2][0]; q2 = sc[3][0];

    const float inv_n  = 1.0f / (float)FH_DIM;
    const float m1 = s1 * inv_n;
    const float m2 = s2 * inv_n;
    // unbiased (ddof=1) std, divide by (std + eps) per reference
    float var1 = fmaxf((q1 - s1 * m1) / (float)(FH_DIM - 1), 0.f);
    float var2 = fmaxf((q2 - s2 * m2) / (float)(FH_DIM - 1), 0.f);
    const float d1 = 1.0f / (sqrtf(var1) + LN_EPS);
    const float d2 = 1.0f / (sqrtf(var2) + LN_EPS);

    // Pass 2: gates + cx_new (each thread owns 4 hidden indices).
    float c_reg[4], o_reg[4];
    float s3 = 0.f, q3 = 0.f;
#pragma unroll
    for (int u = 0; u < 4; u++) {
        const int h = tid + u * 256;

        float xi = fmaf((s_i[h] - m1) * d1, w1[h], b1[h])
                 + fmaf((s_h[h] - m2) * d2, w2[h], b2[h]);
        int jf = h + H_DIM;
        float xf = fmaf((s_i[jf] - m1) * d1, w1[jf], b1[jf])
                 + fmaf((s_h[jf] - m2) * d2, w2[jf], b2[jf]);
        int jo = h + 2 * H_DIM;
        float xo = fmaf((s_i[jo] - m1) * d1, w1[jo], b1[jo])
                 + fmaf((s_h[jo] - m2) * d2, w2[jo], b2[jo]);
        int jc = h + 3 * H_DIM;
        float xc = fmaf((s_i[jc] - m1) * d1, w1[jc], b1[jc])
                 + fmaf((s_h[jc] - m2) * d2, w2[jc], b2[jc]);

        float ig = sigmoidf_(xi);
        float fg = sigmoidf_(xf + FGBIAS);
        float og = sigmoidf_(xo);
        float ct = tanhf(xc);

        float c = fg * cx[(size_t)r * H_DIM + h] + ig * ct;
        c_reg[u] = c;
        o_reg[u] = og;
        s3 += c; q3 += c * c;
        cx_new[(size_t)r * H_DIM + h] = c;
    }

    // LN over cx_new (H elements).
    __syncthreads();   // protect sc reuse
    s3 = warp_sum(s3); q3 = warp_sum(q3);
    if (lane == 0) { sc[0][wrp] = s3; sc[1][wrp] = q3; }
    __syncthreads();
    if (tid == 0) {
        float t0 = 0, t1 = 0;
#pragma unroll
        for (int i = 0; i < 8; i++) { t0 += sc[0][i]; t1 += sc[1][i]; }
        sc[0][0] = t0; sc[1][0] = t1;
    }
    __syncthreads();
    s3 = sc[0][0]; q3 = sc[1][0];

    const float m3 = s3 / (float)H_DIM;
    float var3 = fmaxf((q3 - s3 * m3) / (float)(H_DIM - 1), 0.f);
    const float d3 = 1.0f / (sqrtf(var3) + LN_EPS);

#pragma unroll
    for (int u = 0; u < 4; u++) {
        const int h = tid + u * 256;
        float ln = fmaf((c_reg[u] - m3) * d3, w3[h], b3[h]);
        hx_new[(size_t)r * H_DIM + h] = o_reg[u] * tanhf(ln);
    }
}

// ------------------------------- launcher ----------------------------------
extern "C" void kernel_launch(void* const* d_in, const int* in_sizes, int n_in,
                              void* d_out, int out_size)
{
    const float* inputs   = (const float*)d_in[0];
    const float* hx       = (const float*)d_in[1];
    const float* cx       = (const float*)d_in[2];
    const float* w_i2h    = (const float*)d_in[3];
    const float* b_i2h    = (const float*)d_in[4];
    const float* w_h2h    = (const float*)d_in[5];
    const float* b_h2h    = (const float*)d_in[6];
    const float* ln_i2h_w = (const float*)d_in[7];
    const float* ln_i2h_b = (const float*)d_in[8];
    const float* ln_h2h_w = (const float*)d_in[9];
    const float* ln_h2h_b = (const float*)d_in[10];
    const float* ln_h2o_w = (const float*)d_in[11];
    const float* ln_h2o_b = (const float*)d_in[12];

    float* out    = (float*)d_out;
    float* hx_new = out;                                   // [B,H]
    float* cx_new = out + (size_t)B_DIM * H_DIM;           // [B,H]

    dim3 grid(FH_DIM / BN, B_DIM / BM);   // 32 x 32
    gemm_nt_bias<<<grid, 256>>>(inputs, w_i2h, b_i2h, 0, B_DIM, FH_DIM, K_DIM);
    gemm_nt_bias<<<grid, 256>>>(hx,     w_h2h, b_h2h, 1, B_DIM, FH_DIM, K_DIM);

    lstm_epilogue<<<B_DIM, 256>>>(cx,
                                  ln_i2h_w, ln_i2h_b,
                                  ln_h2h_w, ln_h2h_b,
                                  ln_h2o_w, ln_h2o_b,
                                  hx_new, cx_new);
}

// round 3
// speedup vs baseline: 2.4049x; 2.4049x over previous
#include <cuda_runtime.h>
#include <cuda_bf16.h>
#include <math.h>
#include <stdint.h>

// ---------------------------------------------------------------------------
// LayerNorm LSTM cell, B=4096, I=H=1024.
// GEMMs via mma.sync bf16 (HMMA, baseline sm_103 target), split precision:
//   x = xh + xl (bf16); x@w ~= xh@wh + xh@wl + xl@wh   (error ~2^-16)
// ---------------------------------------------------------------------------

#define B_DIM   4096
#define H_DIM   1024
#define FH_DIM  4096
#define K_DIM   1024
#define LN_EPS  1e-5f
#define FGBIAS  (-1.0f)

// ---------------------------- scratch --------------------------------------
__device__ __nv_bfloat16 g_xh[2][(size_t)B_DIM * K_DIM];   // inputs / hx hi
__device__ __nv_bfloat16 g_xl[2][(size_t)B_DIM * K_DIM];   // inputs / hx lo
__device__ __nv_bfloat16 g_wh[2][(size_t)FH_DIM * K_DIM];  // w_i2h / w_h2h hi
__device__ __nv_bfloat16 g_wl[2][(size_t)FH_DIM * K_DIM];  // w_i2h / w_h2h lo
__device__ float g_i2h[(size_t)B_DIM * FH_DIM];
__device__ float g_h2h[(size_t)B_DIM * FH_DIM];

// ---------------------------- asm helpers ----------------------------------
__device__ __forceinline__ uint32_t smem_u32(const void* p) {
    uint32_t a;
    asm("{ .reg .u64 t; cvta.to.shared.u64 t, %1; cvt.u32.u64 %0, t; }" : "=r"(a) : "l"(p));
    return a;
}

#define CP_ASYNC16(saddr, gptr) \
    asm volatile("cp.async.cg.shared.global [%0], [%1], 16;" :: "r"(saddr), "l"(gptr))
#define CP_COMMIT() asm volatile("cp.async.commit_group;")
#define CP_WAIT(n)  asm volatile("cp.async.wait_group %0;" :: "n"(n))

#define LDSM4(r, addr) \
    asm volatile("ldmatrix.sync.aligned.m8n8.x4.shared.b16 {%0,%1,%2,%3}, [%4];" \
        : "=r"((r)[0]), "=r"((r)[1]), "=r"((r)[2]), "=r"((r)[3]) : "r"(addr))

#define MMA16816(d, a, b) \
    asm volatile("mma.sync.aligned.m16n8k16.row.col.f32.bf16.bf16.f32 " \
        "{%0,%1,%2,%3}, {%4,%5,%6,%7}, {%8,%9}, {%0,%1,%2,%3};" \
        : "+f"((d)[0]), "+f"((d)[1]), "+f"((d)[2]), "+f"((d)[3]) \
        : "r"((a)[0]), "r"((a)[1]), "r"((a)[2]), "r"((a)[3]), \
          "r"((b)[0]), "r"((b)[1]))

// ---------------------- conversion / split kernel ---------------------------
// mat: 0=inputs, 1=hx, 2=w_i2h, 3=w_h2h. All 4096x1024 fp32, row-major.
__global__ __launch_bounds__(256)
void convert_split(const float* __restrict__ src, int mat)
{
    size_t idx = (size_t)blockIdx.x * 256 + threadIdx.x;   // one 8-float chunk
    const float4* s4 = reinterpret_cast<const float4*>(src + idx * 8);
    float4 v0 = s4[0], v1 = s4[1];
    float av[8] = { v0.x, v0.y, v0.z, v0.w, v1.x, v1.y, v1.z, v1.w };

    union { __nv_bfloat16 b[8]; uint4 u; } Hh, Ll;
#pragma unroll
    for (int i = 0; i < 8; i++) {
        __nv_bfloat16 h = __float2bfloat16_rn(av[i]);
        Hh.b[i] = h;
        Ll.b[i] = __float2bfloat16_rn(av[i] - __bfloat162float(h));
    }

    __nv_bfloat16 *hp, *lp;
    switch (mat) {
        case 0:  hp = g_xh[0]; lp = g_xl[0]; break;
        case 1:  hp = g_xh[1]; lp = g_xl[1]; break;
        case 2:  hp = g_wh[0]; lp = g_wl[0]; break;
        default: hp = g_wh[1]; lp = g_wl[1]; break;
    }
    *reinterpret_cast<uint4*>(hp + idx * 8) = Hh.u;
    *reinterpret_cast<uint4*>(lp + idx * 8) = Ll.u;
}

// ------------------------------ HMMA GEMM ----------------------------------
// C[4096,4096] = X[4096,1024] @ W[4096,1024]^T + bias (fp32 out)
// CTA tile 128x128, 8 warps (warp tile 64x32), K chunk 32, 4-stage cp.async.
//
// smem tile layout per operand tile (128 rows x 32 bf16):
//   row pitch 64 B (4 x 16B chunks), chunk swizzle: c' = c ^ ((row>>1)&3)
//   -> conflict-free ldmatrix (verified: granule (4r + c') mod 8 distinct
//      over each 8-address phase).
#define KCH      32
#define NSTAGE   4
#define TILE_B   8192                   // 128 * 64 B
#define STAGE_B  (4 * TILE_B)           // Ah, Al, Wh, Wl
#define GEMM_SMEM (NSTAGE * STAGE_B)    // 131072

__global__ __launch_bounds__(256, 1)
void gemm_tc(const float* __restrict__ bias0, const float* __restrict__ bias1)
{
    extern __shared__ char smem[];
    const uint32_t sbase = smem_u32(smem);
    const int tid = threadIdx.x, wid = tid >> 5, lane = tid & 31;
    const int bx = blockIdx.x, by = blockIdx.y, which = blockIdx.z;

    // ---- cp.async source assignment: 64 threads per operand tile ----
    const int tt  = tid >> 6;          // 0:Ah 1:Al 2:Wh 3:Wl
    const int t64 = tid & 63;
    const __nv_bfloat16* gsrc;
    int rowbase;
    switch (tt) {
        case 0:  gsrc = g_xh[which]; rowbase = by * 128; break;
        case 1:  gsrc = g_xl[which]; rowbase = by * 128; break;
        case 2:  gsrc = g_wh[which]; rowbase = bx * 128; break;
        default: gsrc = g_wl[which]; rowbase = bx * 128; break;
    }

    auto issue_stage = [&](int ks, int st) {
        const uint32_t sdstT = sbase + st * STAGE_B + tt * TILE_B;
        const __nv_bfloat16* g0 = gsrc + (size_t)rowbase * K_DIM + ks * KCH;
#pragma unroll
        for (int j = 0; j < 8; j++) {
            int idx = t64 + 64 * j;
            int row = idx >> 2, c = idx & 3;
            const __nv_bfloat16* g = g0 + (size_t)row * K_DIM + c * 8;
            uint32_t s = sdstT + row * 64 + ((c ^ ((row >> 1) & 3)) << 4);
            CP_ASYNC16(s, g);
        }
        CP_COMMIT();
    };

    // ---- prologue: 3 stages in flight ----
    issue_stage(0, 0);
    issue_stage(1, 1);
    issue_stage(2, 2);

    const int wm = wid & 1;            // 2 m-halves of 64
    const int wn = wid >> 1;           // 4 n-quarters of 32

    float acc[4][4][4];
#pragma unroll
    for (int mi = 0; mi < 4; mi++)
#pragma unroll
        for (int ni = 0; ni < 4; ni++)
#pragma unroll
            for (int q = 0; q < 4; q++) acc[mi][ni][q] = 0.f;

    // Precompute per-lane smem offsets (within a tile) for ldmatrix.
    // A (and W hi/lo use the same pattern for their own row base):
    //   lanes 0-15: rows base+0..15, chunk cc=0 ; lanes 16-31: same rows, cc=1
    const int a_r = (lane & 15);
    const int a_cc = lane >> 4;
    // B: lanes 0-7: n0-7 cc0; 8-15: n0-7 cc1; 16-23: n8-15 cc0; 24-31: n8-15 cc1
    const int b_r = ((lane >> 4) << 3) + (lane & 7);
    const int b_cc = (lane >> 3) & 1;

    for (int kc = 0; kc < K_DIM / KCH; kc++) {
        const int st = kc % NSTAGE;
        CP_WAIT(2);
        __syncthreads();
        if (kc + 3 < K_DIM / KCH) issue_stage(kc + 3, (kc + 3) % NSTAGE);

        const uint32_t base = sbase + st * STAGE_B;

#pragma unroll
        for (int kt = 0; kt < 2; kt++) {
            uint32_t af[4][4], bh[4][2], bl[4][2];

            // A-hi fragments (4 m16 tiles)
#pragma unroll
            for (int mi = 0; mi < 4; mi++) {
                int r = wm * 64 + mi * 16 + a_r;
                int c = 2 * kt + a_cc;
                uint32_t addr = base + r * 64 + ((c ^ ((r >> 1) & 3)) << 4);
                LDSM4(af[mi], addr);
            }
            // W-hi fragments (4 n8 tiles via 2 x ldmatrix.x4)
#pragma unroll
            for (int g = 0; g < 2; g++) {
                int r = wn * 32 + g * 16 + b_r;
                int c = 2 * kt + b_cc;
                uint32_t addr = base + 2 * TILE_B + r * 64 + ((c ^ ((r >> 1) & 3)) << 4);
                uint32_t t[4];
                LDSM4(t, addr);
                bh[2 * g + 0][0] = t[0]; bh[2 * g + 0][1] = t[1];
                bh[2 * g + 1][0] = t[2]; bh[2 * g + 1][1] = t[3];
            }
            // Ah @ Wh
#pragma unroll
            for (int mi = 0; mi < 4; mi++)
#pragma unroll
                for (int ni = 0; ni < 4; ni++)
                    MMA16816(acc[mi][ni], af[mi], bh[ni]);

            // W-lo fragments
#pragma unroll
            for (int g = 0; g < 2; g++) {
                int r = wn * 32 + g * 16 + b_r;
                int c = 2 * kt + b_cc;
                uint32_t addr = base + 3 * TILE_B + r * 64 + ((c ^ ((r >> 1) & 3)) << 4);
                uint32_t t[4];
                LDSM4(t, addr);
                bl[2 * g + 0][0] = t[0]; bl[2 * g + 0][1] = t[1];
                bl[2 * g + 1][0] = t[2]; bl[2 * g + 1][1] = t[3];
            }
            // Ah @ Wl
#pragma unroll
            for (int mi = 0; mi < 4; mi++)
#pragma unroll
                for (int ni = 0; ni < 4; ni++)
                    MMA16816(acc[mi][ni], af[mi], bl[ni]);

            // A-lo fragments (reuse af regs)
#pragma unroll
            for (int mi = 0; mi < 4; mi++) {
                int r = wm * 64 + mi * 16 + a_r;
                int c = 2 * kt + a_cc;
                uint32_t addr = base + TILE_B + r * 64 + ((c ^ ((r >> 1) & 3)) << 4);
                LDSM4(af[mi], addr);
            }
            // Al @ Wh
#pragma unroll
            for (int mi = 0; mi < 4; mi++)
#pragma unroll
                for (int ni = 0; ni < 4; ni++)
                    MMA16816(acc[mi][ni], af[mi], bh[ni]);
        }
    }

    // ---- epilogue: bias + store fp32 ----
    const float* bias = which ? bias1 : bias0;
    float* C = which ? g_h2h : g_i2h;
    const int mrow0 = by * 128 + wm * 64;
    const int ncol0 = bx * 128 + wn * 32;
#pragma unroll
    for (int mi = 0; mi < 4; mi++) {
        const int r0 = mrow0 + mi * 16 + (lane >> 2);
#pragma unroll
        for (int ni = 0; ni < 4; ni++) {
            const int cc = ncol0 + ni * 8 + (lane & 3) * 2;
            const float b0 = __ldg(bias + cc), b1 = __ldg(bias + cc + 1);
            float2 v0 = make_float2(acc[mi][ni][0] + b0, acc[mi][ni][1] + b1);
            float2 v1 = make_float2(acc[mi][ni][2] + b0, acc[mi][ni][3] + b1);
            *reinterpret_cast<float2*>(C + (size_t)r0 * FH_DIM + cc) = v0;
            *reinterpret_cast<float2*>(C + (size_t)(r0 + 8) * FH_DIM + cc) = v1;
        }
    }
}

// --------------------------- fused LN/gate epilogue ------------------------
__device__ __forceinline__ float warp_sum(float v) {
#pragma unroll
    for (int o = 16; o; o >>= 1) v += __shfl_down_sync(0xffffffffu, v, o);
    return v;
}
__device__ __forceinline__ float sigmoidf_(float x) { return 1.0f / (1.0f + expf(-x)); }

__global__ __launch_bounds__(256)
void lstm_epilogue(const float* __restrict__ cx,
                   const float* __restrict__ w1, const float* __restrict__ b1,
                   const float* __restrict__ w2, const float* __restrict__ b2,
                   const float* __restrict__ w3, const float* __restrict__ b3,
                   float* __restrict__ hx_new,
                   float* __restrict__ cx_new)
{
    const int r   = blockIdx.x;
    const int tid = threadIdx.x;
    const int lane = tid & 31;
    const int wrp  = tid >> 5;

    const float* __restrict__ ri = g_i2h + (size_t)r * FH_DIM;
    const float* __restrict__ rh = g_h2h + (size_t)r * FH_DIM;

    __shared__ float s_i[FH_DIM];
    __shared__ float s_h[FH_DIM];
    __shared__ float sc[4][8];

    float s1 = 0.f, q1 = 0.f, s2 = 0.f, q2 = 0.f;
    for (int j = tid; j < FH_DIM; j += 256) {
        float a = ri[j], b = rh[j];
        s_i[j] = a; s_h[j] = b;
        s1 += a; q1 += a * a;
        s2 += b; q2 += b * b;
    }
    s1 = warp_sum(s1); q1 = warp_sum(q1);
    s2 = warp_sum(s2); q2 = warp_sum(q2);
    if (lane == 0) { sc[0][wrp] = s1; sc[1][wrp] = q1; sc[2][wrp] = s2; sc[3][wrp] = q2; }
    __syncthreads();
    if (tid == 0) {
        float t0 = 0, t1 = 0, t2 = 0, t3 = 0;
#pragma unroll
        for (int i = 0; i < 8; i++) { t0 += sc[0][i]; t1 += sc[1][i]; t2 += sc[2][i]; t3 += sc[3][i]; }
        sc[0][0] = t0; sc[1][0] = t1; sc[2][0] = t2; sc[3][0] = t3;
    }
    __syncthreads();
    s1 = sc[0][0]; q1 = sc[1][0]; s2 = sc[2][0]; q2 = sc[3][0];

    const float inv_n = 1.0f / (float)FH_DIM;
    const float m1 = s1 * inv_n;
    const float m2 = s2 * inv_n;
    float var1 = fmaxf((q1 - s1 * m1) / (float)(FH_DIM - 1), 0.f);
    float var2 = fmaxf((q2 - s2 * m2) / (float)(FH_DIM - 1), 0.f);
    const float d1 = 1.0f / (sqrtf(var1) + LN_EPS);
    const float d2 = 1.0f / (sqrtf(var2) + LN_EPS);

    float c_reg[4], o_reg[4];
    float s3 = 0.f, q3 = 0.f;
#pragma unroll
    for (int u = 0; u < 4; u++) {
        const int h = tid + u * 256;

        float xi = fmaf((s_i[h] - m1) * d1, w1[h], b1[h])
                 + fmaf((s_h[h] - m2) * d2, w2[h], b2[h]);
        int jf = h + H_DIM;
        float xf = fmaf((s_i[jf] - m1) * d1, w1[jf], b1[jf])
                 + fmaf((s_h[jf] - m2) * d2, w2[jf], b2[jf]);
        int jo = h + 2 * H_DIM;
        float xo = fmaf((s_i[jo] - m1) * d1, w1[jo], b1[jo])
                 + fmaf((s_h[jo] - m2) * d2, w2[jo], b2[jo]);
        int jc = h + 3 * H_DIM;
        float xc = fmaf((s_i[jc] - m1) * d1, w1[jc], b1[jc])
                 + fmaf((s_h[jc] - m2) * d2, w2[jc], b2[jc]);

        float ig = sigmoidf_(xi);
        float fg = sigmoidf_(xf + FGBIAS);
        float og = sigmoidf_(xo);
        float ct = tanhf(xc);

        float c = fg * cx[(size_t)r * H_DIM + h] + ig * ct;
        c_reg[u] = c;
        o_reg[u] = og;
        s3 += c; q3 += c * c;
        cx_new[(size_t)r * H_DIM + h] = c;
    }

    __syncthreads();
    s3 = warp_sum(s3); q3 = warp_sum(q3);
    if (lane == 0) { sc[0][wrp] = s3; sc[1][wrp] = q3; }
    __syncthreads();
    if (tid == 0) {
        float t0 = 0, t1 = 0;
#pragma unroll
        for (int i = 0; i < 8; i++) { t0 += sc[0][i]; t1 += sc[1][i]; }
        sc[0][0] = t0; sc[1][0] = t1;
    }
    __syncthreads();
    s3 = sc[0][0]; q3 = sc[1][0];

    const float m3 = s3 / (float)H_DIM;
    float var3 = fmaxf((q3 - s3 * m3) / (float)(H_DIM - 1), 0.f);
    const float d3 = 1.0f / (sqrtf(var3) + LN_EPS);

#pragma unroll
    for (int u = 0; u < 4; u++) {
        const int h = tid + u * 256;
        float ln = fmaf((c_reg[u] - m3) * d3, w3[h], b3[h]);
        hx_new[(size_t)r * H_DIM + h] = o_reg[u] * tanhf(ln);
    }
}

// ------------------------------- launcher ----------------------------------
extern "C" void kernel_launch(void* const* d_in, const int* in_sizes, int n_in,
                              void* d_out, int out_size)
{
    const float* inputs   = (const float*)d_in[0];
    const float* hx       = (const float*)d_in[1];
    const float* cx       = (const float*)d_in[2];
    const float* w_i2h    = (const float*)d_in[3];
    const float* b_i2h    = (const float*)d_in[4];
    const float* w_h2h    = (const float*)d_in[5];
    const float* b_h2h    = (const float*)d_in[6];
    const float* ln_i2h_w = (const float*)d_in[7];
    const float* ln_i2h_b = (const float*)d_in[8];
    const float* ln_h2h_w = (const float*)d_in[9];
    const float* ln_h2h_b = (const float*)d_in[10];
    const float* ln_h2o_w = (const float*)d_in[11];
    const float* ln_h2o_b = (const float*)d_in[12];

    float* out    = (float*)d_out;
    float* hx_new = out;
    float* cx_new = out + (size_t)B_DIM * H_DIM;

    static int smem_set = 0;
    if (!smem_set) {
        cudaFuncSetAttribute(gemm_tc, cudaFuncAttributeMaxDynamicSharedMemorySize, GEMM_SMEM);
        smem_set = 1;
    }

    convert_split<<<2048, 256>>>(inputs, 0);
    convert_split<<<2048, 256>>>(hx,     1);
    convert_split<<<2048, 256>>>(w_i2h,  2);
    convert_split<<<2048, 256>>>(w_h2h,  3);

    gemm_tc<<<dim3(FH_DIM / 128, B_DIM / 128, 2), 256, GEMM_SMEM>>>(b_i2h, b_h2h);

    lstm_epilogue<<<B_DIM, 256>>>(cx,
                                  ln_i2h_w, ln_i2h_b,
                                  ln_h2h_w, ln_h2h_b,
                                  ln_h2o_w, ln_h2o_b,
                                  hx_new, cx_new);
}

// round 4
// speedup vs baseline: 3.9568x; 1.6453x over previous
#include <cuda_runtime.h>
#include <cuda_fp16.h>
#include <math.h>
#include <stdint.h>

// ---------------------------------------------------------------------------
// LayerNorm LSTM cell, B=4096, I=H=1024.
// GEMMs via mma.sync fp16 (HMMA), 2-pass split precision:
//   A = Ah + Al (fp16), W ~ Wh (fp16);  A@W ~= Ah@Wh + Al@Wh
//   uncorrected W-rounding error ~2^-11 -> output rel err ~1e-4.
// ---------------------------------------------------------------------------

#define B_DIM   4096
#define H_DIM   1024
#define FH_DIM  4096
#define K_DIM   1024
#define LN_EPS  1e-5f
#define FGBIAS  (-1.0f)

// ---------------------------- scratch --------------------------------------
__device__ __half g_xh[2][(size_t)B_DIM * K_DIM];   // inputs / hx hi
__device__ __half g_xl[2][(size_t)B_DIM * K_DIM];   // inputs / hx lo
__device__ __half g_wh[2][(size_t)FH_DIM * K_DIM];  // w_i2h / w_h2h (fp16)
__device__ float g_i2h[(size_t)B_DIM * FH_DIM];
__device__ float g_h2h[(size_t)B_DIM * FH_DIM];

// ---------------------------- asm helpers ----------------------------------
__device__ __forceinline__ uint32_t smem_u32(const void* p) {
    uint32_t a;
    asm("{ .reg .u64 t; cvta.to.shared.u64 t, %1; cvt.u32.u64 %0, t; }" : "=r"(a) : "l"(p));
    return a;
}

#define CP_ASYNC16(saddr, gptr) \
    asm volatile("cp.async.cg.shared.global [%0], [%1], 16;" :: "r"(saddr), "l"(gptr))
#define CP_COMMIT() asm volatile("cp.async.commit_group;")
#define CP_WAIT(n)  asm volatile("cp.async.wait_group %0;" :: "n"(n))

#define LDSM4(r, addr) \
    asm volatile("ldmatrix.sync.aligned.m8n8.x4.shared.b16 {%0,%1,%2,%3}, [%4];" \
        : "=r"((r)[0]), "=r"((r)[1]), "=r"((r)[2]), "=r"((r)[3]) : "r"(addr))

#define MMA16816(d, a, b) \
    asm volatile("mma.sync.aligned.m16n8k16.row.col.f32.f16.f16.f32 " \
        "{%0,%1,%2,%3}, {%4,%5,%6,%7}, {%8,%9}, {%0,%1,%2,%3};" \
        : "+f"((d)[0]), "+f"((d)[1]), "+f"((d)[2]), "+f"((d)[3]) \
        : "r"((a)[0]), "r"((a)[1]), "r"((a)[2]), "r"((a)[3]), \
          "r"((b)[0]), "r"((b)[1]))

// ---------------------- conversion / split kernel ---------------------------
// grid.y selects matrix: 0=inputs (split), 1=hx (split), 2=w_i2h, 3=w_h2h.
__global__ __launch_bounds__(256)
void convert_split(const float* __restrict__ inputs, const float* __restrict__ hx,
                   const float* __restrict__ w0, const float* __restrict__ w1)
{
    const int mat = blockIdx.y;
    const float* src;
    switch (mat) {
        case 0:  src = inputs; break;
        case 1:  src = hx;     break;
        case 2:  src = w0;     break;
        default: src = w1;     break;
    }
    size_t idx = (size_t)blockIdx.x * 256 + threadIdx.x;   // one 8-float chunk
    const float4* s4 = reinterpret_cast<const float4*>(src + idx * 8);
    float4 v0 = s4[0], v1 = s4[1];
    float av[8] = { v0.x, v0.y, v0.z, v0.w, v1.x, v1.y, v1.z, v1.w };

    union { __half b[8]; uint4 u; } Hh, Ll;
#pragma unroll
    for (int i = 0; i < 8; i++) {
        __half h = __float2half_rn(av[i]);
        Hh.b[i] = h;
        Ll.b[i] = __float2half_rn(av[i] - __half2float(h));
    }

    if (mat < 2) {
        *reinterpret_cast<uint4*>(g_xh[mat] + idx * 8) = Hh.u;
        *reinterpret_cast<uint4*>(g_xl[mat] + idx * 8) = Ll.u;
    } else {
        *reinterpret_cast<uint4*>(g_wh[mat - 2] + idx * 8) = Hh.u;
    }
}

// ------------------------------ HMMA GEMM ----------------------------------
// C[4096,4096] = X[4096,1024] @ W[4096,1024]^T + bias (fp32 out)
// CTA tile 128x128, 8 warps (warp tile 64x32), K chunk 32, 4-stage cp.async,
// 2 CTAs/SM. smem tile: 128 rows x 64B, chunk swizzle c' = c ^ ((row>>1)&3).
#define KCH      32
#define NSTAGE   4
#define TILE_B   8192                    // 128 * 64 B
#define STAGE_B  (3 * TILE_B)            // Ah, Al, Wh
#define GEMM_SMEM (NSTAGE * STAGE_B)     // 98304

__global__ __launch_bounds__(256, 2)
void gemm_tc(const float* __restrict__ bias0, const float* __restrict__ bias1)
{
    extern __shared__ char smem[];
    const uint32_t sbase = smem_u32(smem);
    const int tid = threadIdx.x, wid = tid >> 5, lane = tid & 31;
    const int bx = blockIdx.x, by = blockIdx.y, which = blockIdx.z;

    const __half* srcAh = g_xh[which] + (size_t)(by * 128) * K_DIM;
    const __half* srcAl = g_xl[which] + (size_t)(by * 128) * K_DIM;
    const __half* srcW  = g_wh[which] + (size_t)(bx * 128) * K_DIM;

    auto issue_stage = [&](int ks, int st) {
        const uint32_t sdst = sbase + st * STAGE_B;
#pragma unroll
        for (int j = 0; j < 6; j++) {
            int idx = tid + 256 * j;              // 0..1535
            int tile = idx >> 9;                  // 0..2
            int w = idx & 511;
            int row = w >> 2, c = w & 3;
            const __half* gb = (tile == 0) ? srcAh : (tile == 1) ? srcAl : srcW;
            const __half* g = gb + (size_t)row * K_DIM + ks * KCH + c * 8;
            uint32_t s = sdst + tile * TILE_B + row * 64 + ((c ^ ((row >> 1) & 3)) << 4);
            CP_ASYNC16(s, g);
        }
        CP_COMMIT();
    };

    issue_stage(0, 0);
    issue_stage(1, 1);
    issue_stage(2, 2);

    const int wm = wid & 1;            // 2 m-halves of 64
    const int wn = wid >> 1;           // 4 n-quarters of 32

    float acc[4][4][4];
#pragma unroll
    for (int mi = 0; mi < 4; mi++)
#pragma unroll
        for (int ni = 0; ni < 4; ni++)
#pragma unroll
            for (int q = 0; q < 4; q++) acc[mi][ni][q] = 0.f;

    const int a_r = (lane & 15);
    const int a_cc = lane >> 4;
    const int b_r = ((lane >> 4) << 3) + (lane & 7);
    const int b_cc = (lane >> 3) & 1;

    for (int kc = 0; kc < K_DIM / KCH; kc++) {
        const int st = kc % NSTAGE;
        CP_WAIT(2);
        __syncthreads();
        if (kc + 3 < K_DIM / KCH) issue_stage(kc + 3, (kc + 3) % NSTAGE);

        const uint32_t base = sbase + st * STAGE_B;

#pragma unroll
        for (int kt = 0; kt < 2; kt++) {
            uint32_t af[4][4], bh[4][2];

            // W fragments (4 n8 tiles via 2 x ldmatrix.x4)
#pragma unroll
            for (int g = 0; g < 2; g++) {
                int r = wn * 32 + g * 16 + b_r;
                int c = 2 * kt + b_cc;
                uint32_t addr = base + 2 * TILE_B + r * 64 + ((c ^ ((r >> 1) & 3)) << 4);
                uint32_t t[4];
                LDSM4(t, addr);
                bh[2 * g + 0][0] = t[0]; bh[2 * g + 0][1] = t[1];
                bh[2 * g + 1][0] = t[2]; bh[2 * g + 1][1] = t[3];
            }
            // A-hi fragments
#pragma unroll
            for (int mi = 0; mi < 4; mi++) {
                int r = wm * 64 + mi * 16 + a_r;
                int c = 2 * kt + a_cc;
                uint32_t addr = base + r * 64 + ((c ^ ((r >> 1) & 3)) << 4);
                LDSM4(af[mi], addr);
            }
#pragma unroll
            for (int mi = 0; mi < 4; mi++)
#pragma unroll
                for (int ni = 0; ni < 4; ni++)
                    MMA16816(acc[mi][ni], af[mi], bh[ni]);

            // A-lo fragments (reuse af regs)
#pragma unroll
            for (int mi = 0; mi < 4; mi++) {
                int r = wm * 64 + mi * 16 + a_r;
                int c = 2 * kt + a_cc;
                uint32_t addr = base + TILE_B + r * 64 + ((c ^ ((r >> 1) & 3)) << 4);
                LDSM4(af[mi], addr);
            }
#pragma unroll
            for (int mi = 0; mi < 4; mi++)
#pragma unroll
                for (int ni = 0; ni < 4; ni++)
                    MMA16816(acc[mi][ni], af[mi], bh[ni]);
        }
    }

    // ---- epilogue: bias + store fp32 ----
    const float* bias = which ? bias1 : bias0;
    float* C = which ? g_h2h : g_i2h;
    const int mrow0 = by * 128 + wm * 64;
    const int ncol0 = bx * 128 + wn * 32;
#pragma unroll
    for (int mi = 0; mi < 4; mi++) {
        const int r0 = mrow0 + mi * 16 + (lane >> 2);
#pragma unroll
        for (int ni = 0; ni < 4; ni++) {
            const int cc = ncol0 + ni * 8 + (lane & 3) * 2;
            const float b0 = __ldg(bias + cc), b1 = __ldg(bias + cc + 1);
            float2 v0 = make_float2(acc[mi][ni][0] + b0, acc[mi][ni][1] + b1);
            float2 v1 = make_float2(acc[mi][ni][2] + b0, acc[mi][ni][3] + b1);
            *reinterpret_cast<float2*>(C + (size_t)r0 * FH_DIM + cc) = v0;
            *reinterpret_cast<float2*>(C + (size_t)(r0 + 8) * FH_DIM + cc) = v1;
        }
    }
}

// --------------------------- fused LN/gate epilogue ------------------------
__device__ __forceinline__ float warp_sum(float v) {
#pragma unroll
    for (int o = 16; o; o >>= 1) v += __shfl_down_sync(0xffffffffu, v, o);
    return v;
}
__device__ __forceinline__ float sigmoidf_(float x) { return 1.0f / (1.0f + expf(-x)); }

__global__ __launch_bounds__(256)
void lstm_epilogue(const float* __restrict__ cx,
                   const float* __restrict__ w1, const float* __restrict__ b1,
                   const float* __restrict__ w2, const float* __restrict__ b2,
                   const float* __restrict__ w3, const float* __restrict__ b3,
                   float* __restrict__ hx_new,
                   float* __restrict__ cx_new)
{
    const int r   = blockIdx.x;
    const int tid = threadIdx.x;
    const int lane = tid & 31;
    const int wrp  = tid >> 5;

    const float4* __restrict__ ri4 =
        reinterpret_cast<const float4*>(g_i2h + (size_t)r * FH_DIM);
    const float4* __restrict__ rh4 =
        reinterpret_cast<const float4*>(g_h2h + (size_t)r * FH_DIM);

    __shared__ float s_i[FH_DIM];
    __shared__ float s_h[FH_DIM];
    __shared__ float sc[4][8];
    float4* s_i4 = reinterpret_cast<float4*>(s_i);
    float4* s_h4 = reinterpret_cast<float4*>(s_h);

    float s1 = 0.f, q1 = 0.f, s2 = 0.f, q2 = 0.f;
#pragma unroll
    for (int u = 0; u < 4; u++) {
        int j = tid + u * 256;                 // float4 index 0..1023
        float4 a = ri4[j], b = rh4[j];
        s_i4[j] = a; s_h4[j] = b;
        s1 += a.x + a.y + a.z + a.w;
        q1 += a.x * a.x + a.y * a.y + a.z * a.z + a.w * a.w;
        s2 += b.x + b.y + b.z + b.w;
        q2 += b.x * b.x + b.y * b.y + b.z * b.z + b.w * b.w;
    }
    s1 = warp_sum(s1); q1 = warp_sum(q1);
    s2 = warp_sum(s2); q2 = warp_sum(q2);
    if (lane == 0) { sc[0][wrp] = s1; sc[1][wrp] = q1; sc[2][wrp] = s2; sc[3][wrp] = q2; }
    __syncthreads();
    if (tid == 0) {
        float t0 = 0, t1 = 0, t2 = 0, t3 = 0;
#pragma unroll
        for (int i = 0; i < 8; i++) { t0 += sc[0][i]; t1 += sc[1][i]; t2 += sc[2][i]; t3 += sc[3][i]; }
        sc[0][0] = t0; sc[1][0] = t1; sc[2][0] = t2; sc[3][0] = t3;
    }
    __syncthreads();
    s1 = sc[0][0]; q1 = sc[1][0]; s2 = sc[2][0]; q2 = sc[3][0];

    const float inv_n = 1.0f / (float)FH_DIM;
    const float m1 = s1 * inv_n;
    const float m2 = s2 * inv_n;
    float var1 = fmaxf((q1 - s1 * m1) / (float)(FH_DIM - 1), 0.f);
    float var2 = fmaxf((q2 - s2 * m2) / (float)(FH_DIM - 1), 0.f);
    const float d1 = 1.0f / (sqrtf(var1) + LN_EPS);
    const float d2 = 1.0f / (sqrtf(var2) + LN_EPS);

    float c_reg[4], o_reg[4];
    float s3 = 0.f, q3 = 0.f;
#pragma unroll
    for (int u = 0; u < 4; u++) {
        const int h = tid + u * 256;

        float xi = fmaf((s_i[h] - m1) * d1, w1[h], b1[h])
                 + fmaf((s_h[h] - m2) * d2, w2[h], b2[h]);
        int jf = h + H_DIM;
        float xf = fmaf((s_i[jf] - m1) * d1, w1[jf], b1[jf])
                 + fmaf((s_h[jf] - m2) * d2, w2[jf], b2[jf]);
        int jo = h + 2 * H_DIM;
        float xo = fmaf((s_i[jo] - m1) * d1, w1[jo], b1[jo])
                 + fmaf((s_h[jo] - m2) * d2, w2[jo], b2[jo]);
        int jc = h + 3 * H_DIM;
        float xc = fmaf((s_i[jc] - m1) * d1, w1[jc], b1[jc])
                 + fmaf((s_h[jc] - m2) * d2, w2[jc], b2[jc]);

        float ig = sigmoidf_(xi);
        float fg = sigmoidf_(xf + FGBIAS);
        float og = sigmoidf_(xo);
        float ct = tanhf(xc);

        float c = fg * cx[(size_t)r * H_DIM + h] + ig * ct;
        c_reg[u] = c;
        o_reg[u] = og;
        s3 += c; q3 += c * c;
        cx_new[(size_t)r * H_DIM + h] = c;
    }

    __syncthreads();
    s3 = warp_sum(s3); q3 = warp_sum(q3);
    if (lane == 0) { sc[0][wrp] = s3; sc[1][wrp] = q3; }
    __syncthreads();
    if (tid == 0) {
        float t0 = 0, t1 = 0;
#pragma unroll
        for (int i = 0; i < 8; i++) { t0 += sc[0][i]; t1 += sc[1][i]; }
        sc[0][0] = t0; sc[1][0] = t1;
    }
    __syncthreads();
    s3 = sc[0][0]; q3 = sc[1][0];

    const float m3 = s3 / (float)H_DIM;
    float var3 = fmaxf((q3 - s3 * m3) / (float)(H_DIM - 1), 0.f);
    const float d3 = 1.0f / (sqrtf(var3) + LN_EPS);

#pragma unroll
    for (int u = 0; u < 4; u++) {
        const int h = tid + u * 256;
        float ln = fmaf((c_reg[u] - m3) * d3, w3[h], b3[h]);
        hx_new[(size_t)r * H_DIM + h] = o_reg[u] * tanhf(ln);
    }
}

// ------------------------------- launcher ----------------------------------
extern "C" void kernel_launch(void* const* d_in, const int* in_sizes, int n_in,
                              void* d_out, int out_size)
{
    const float* inputs   = (const float*)d_in[0];
    const float* hx       = (const float*)d_in[1];
    const float* cx       = (const float*)d_in[2];
    const float* w_i2h    = (const float*)d_in[3];
    const float* b_i2h    = (const float*)d_in[4];
    const float* w_h2h    = (const float*)d_in[5];
    const float* b_h2h    = (const float*)d_in[6];
    const float* ln_i2h_w = (const float*)d_in[7];
    const float* ln_i2h_b = (const float*)d_in[8];
    const float* ln_h2h_w = (const float*)d_in[9];
    const float* ln_h2h_b = (const float*)d_in[10];
    const float* ln_h2o_w = (const float*)d_in[11];
    const float* ln_h2o_b = (const float*)d_in[12];

    float* out    = (float*)d_out;
    float* hx_new = out;
    float* cx_new = out + (size_t)B_DIM * H_DIM;

    static int smem_set = 0;
    if (!smem_set) {
        cudaFuncSetAttribute(gemm_tc, cudaFuncAttributeMaxDynamicSharedMemorySize, GEMM_SMEM);
        smem_set = 1;
    }

    convert_split<<<dim3(2048, 4), 256>>>(inputs, hx, w_i2h, w_h2h);

    gemm_tc<<<dim3(FH_DIM / 128, B_DIM / 128, 2), 256, GEMM_SMEM>>>(b_i2h, b_h2h);

    lstm_epilogue<<<B_DIM, 256>>>(cx,
                                  ln_i2h_w, ln_i2h_b,
                                  ln_h2h_w, ln_h2h_b,
                                  ln_h2o_w, ln_h2o_b,
                                  hx_new, cx_new);
}

// round 5
// speedup vs baseline: 5.9030x; 1.4919x over previous
#include <cuda_runtime.h>
#include <cuda_fp16.h>
#include <math.h>
#include <stdint.h>

// ---------------------------------------------------------------------------
// LayerNorm LSTM cell, B=4096, I=H=1024.
// GEMMs via mma.sync fp16 (HMMA), single pass:
//   A ~ Ah (fp16), W ~ Wh (fp16); rounding error ~2^-11 each side,
//   measured-anchored output rel err ~3e-4 (gate: 1e-3).
// ---------------------------------------------------------------------------

#define B_DIM   4096
#define H_DIM   1024
#define FH_DIM  4096
#define K_DIM   1024
#define LN_EPS  1e-5f
#define FGBIAS  (-1.0f)

// ---------------------------- scratch --------------------------------------
__device__ __half g_xh[2][(size_t)B_DIM * K_DIM];   // inputs / hx (fp16)
__device__ __half g_wh[2][(size_t)FH_DIM * K_DIM];  // w_i2h / w_h2h (fp16)
__device__ float g_i2h[(size_t)B_DIM * FH_DIM];
__device__ float g_h2h[(size_t)B_DIM * FH_DIM];

// ---------------------------- asm helpers ----------------------------------
__device__ __forceinline__ uint32_t smem_u32(const void* p) {
    uint32_t a;
    asm("{ .reg .u64 t; cvta.to.shared.u64 t, %1; cvt.u32.u64 %0, t; }" : "=r"(a) : "l"(p));
    return a;
}

#define CP_ASYNC16(saddr, gptr) \
    asm volatile("cp.async.cg.shared.global [%0], [%1], 16;" :: "r"(saddr), "l"(gptr))
#define CP_COMMIT() asm volatile("cp.async.commit_group;")
#define CP_WAIT(n)  asm volatile("cp.async.wait_group %0;" :: "n"(n))

#define LDSM4(r, addr) \
    asm volatile("ldmatrix.sync.aligned.m8n8.x4.shared.b16 {%0,%1,%2,%3}, [%4];" \
        : "=r"((r)[0]), "=r"((r)[1]), "=r"((r)[2]), "=r"((r)[3]) : "r"(addr))

#define MMA16816(d, a, b) \
    asm volatile("mma.sync.aligned.m16n8k16.row.col.f32.f16.f16.f32 " \
        "{%0,%1,%2,%3}, {%4,%5,%6,%7}, {%8,%9}, {%0,%1,%2,%3};" \
        : "+f"((d)[0]), "+f"((d)[1]), "+f"((d)[2]), "+f"((d)[3]) \
        : "r"((a)[0]), "r"((a)[1]), "r"((a)[2]), "r"((a)[3]), \
          "r"((b)[0]), "r"((b)[1]))

// ---------------------- conversion kernel ----------------------------------
// grid.y selects matrix: 0=inputs, 1=hx, 2=w_i2h, 3=w_h2h.
__global__ __launch_bounds__(256)
void convert_fp16(const float* __restrict__ inputs, const float* __restrict__ hx,
                  const float* __restrict__ w0, const float* __restrict__ w1)
{
    const int mat = blockIdx.y;
    const float* src;
    switch (mat) {
        case 0:  src = inputs; break;
        case 1:  src = hx;     break;
        case 2:  src = w0;     break;
        default: src = w1;     break;
    }
    size_t idx = (size_t)blockIdx.x * 256 + threadIdx.x;   // one 8-float chunk
    const float4* s4 = reinterpret_cast<const float4*>(src + idx * 8);
    float4 v0 = s4[0], v1 = s4[1];
    float av[8] = { v0.x, v0.y, v0.z, v0.w, v1.x, v1.y, v1.z, v1.w };

    union { __half b[8]; uint4 u; } Hh;
#pragma unroll
    for (int i = 0; i < 8; i++) Hh.b[i] = __float2half_rn(av[i]);

    __half* hp = (mat < 2) ? g_xh[mat] : g_wh[mat - 2];
    *reinterpret_cast<uint4*>(hp + idx * 8) = Hh.u;
}

// ------------------------------ HMMA GEMM ----------------------------------
// C[4096,4096] = X[4096,1024] @ W[4096,1024]^T + bias (fp32 out)
// CTA tile 128x128, 8 warps (warp tile 64x32), K chunk 32, 4-stage cp.async,
// 2 CTAs/SM. smem tile: 128 rows x 64B, chunk swizzle c' = c ^ ((row>>1)&3).
#define KCH      32
#define NSTAGE   4
#define TILE_B   8192                    // 128 * 64 B
#define STAGE_B  (2 * TILE_B)            // A, W
#define GEMM_SMEM (NSTAGE * STAGE_B)     // 65536

__global__ __launch_bounds__(256, 2)
void gemm_tc(const float* __restrict__ bias0, const float* __restrict__ bias1)
{
    extern __shared__ char smem[];
    const uint32_t sbase = smem_u32(smem);
    const int tid = threadIdx.x, wid = tid >> 5, lane = tid & 31;
    const int bx = blockIdx.x, by = blockIdx.y, which = blockIdx.z;

    const __half* srcA = g_xh[which] + (size_t)(by * 128) * K_DIM;
    const __half* srcW = g_wh[which] + (size_t)(bx * 128) * K_DIM;

    auto issue_stage = [&](int ks, int st) {
        const uint32_t sdst = sbase + st * STAGE_B;
#pragma unroll
        for (int j = 0; j < 4; j++) {
            int idx = tid + 256 * j;              // 0..1023
            int tile = idx >> 9;                  // 0..1
            int w = idx & 511;
            int row = w >> 2, c = w & 3;
            const __half* gb = (tile == 0) ? srcA : srcW;
            const __half* g = gb + (size_t)row * K_DIM + ks * KCH + c * 8;
            uint32_t s = sdst + tile * TILE_B + row * 64 + ((c ^ ((row >> 1) & 3)) << 4);
            CP_ASYNC16(s, g);
        }
        CP_COMMIT();
    };

    issue_stage(0, 0);
    issue_stage(1, 1);
    issue_stage(2, 2);

    const int wm = wid & 1;            // 2 m-halves of 64
    const int wn = wid >> 1;           // 4 n-quarters of 32

    float acc[4][4][4];
#pragma unroll
    for (int mi = 0; mi < 4; mi++)
#pragma unroll
        for (int ni = 0; ni < 4; ni++)
#pragma unroll
            for (int q = 0; q < 4; q++) acc[mi][ni][q] = 0.f;

    const int a_r = (lane & 15);
    const int a_cc = lane >> 4;
    const int b_r = ((lane >> 4) << 3) + (lane & 7);
    const int b_cc = (lane >> 3) & 1;

    for (int kc = 0; kc < K_DIM / KCH; kc++) {
        const int st = kc % NSTAGE;
        CP_WAIT(2);
        __syncthreads();
        if (kc + 3 < K_DIM / KCH) issue_stage(kc + 3, (kc + 3) % NSTAGE);

        const uint32_t base = sbase + st * STAGE_B;

#pragma unroll
        for (int kt = 0; kt < 2; kt++) {
            uint32_t af[4][4], bh[4][2];

            // W fragments (4 n8 tiles via 2 x ldmatrix.x4)
#pragma unroll
            for (int g = 0; g < 2; g++) {
                int r = wn * 32 + g * 16 + b_r;
                int c = 2 * kt + b_cc;
                uint32_t addr = base + TILE_B + r * 64 + ((c ^ ((r >> 1) & 3)) << 4);
                uint32_t t[4];
                LDSM4(t, addr);
                bh[2 * g + 0][0] = t[0]; bh[2 * g + 0][1] = t[1];
                bh[2 * g + 1][0] = t[2]; bh[2 * g + 1][1] = t[3];
            }
            // A fragments
#pragma unroll
            for (int mi = 0; mi < 4; mi++) {
                int r = wm * 64 + mi * 16 + a_r;
                int c = 2 * kt + a_cc;
                uint32_t addr = base + r * 64 + ((c ^ ((r >> 1) & 3)) << 4);
                LDSM4(af[mi], addr);
            }
#pragma unroll
            for (int mi = 0; mi < 4; mi++)
#pragma unroll
                for (int ni = 0; ni < 4; ni++)
                    MMA16816(acc[mi][ni], af[mi], bh[ni]);
        }
    }

    // ---- epilogue: bias + store fp32 ----
    const float* bias = which ? bias1 : bias0;
    float* C = which ? g_h2h : g_i2h;
    const int mrow0 = by * 128 + wm * 64;
    const int ncol0 = bx * 128 + wn * 32;
#pragma unroll
    for (int mi = 0; mi < 4; mi++) {
        const int r0 = mrow0 + mi * 16 + (lane >> 2);
#pragma unroll
        for (int ni = 0; ni < 4; ni++) {
            const int cc = ncol0 + ni * 8 + (lane & 3) * 2;
            const float b0 = __ldg(bias + cc), b1 = __ldg(bias + cc + 1);
            float2 v0 = make_float2(acc[mi][ni][0] + b0, acc[mi][ni][1] + b1);
            float2 v1 = make_float2(acc[mi][ni][2] + b0, acc[mi][ni][3] + b1);
            *reinterpret_cast<float2*>(C + (size_t)r0 * FH_DIM + cc) = v0;
            *reinterpret_cast<float2*>(C + (size_t)(r0 + 8) * FH_DIM + cc) = v1;
        }
    }
}

// --------------------------- fused LN/gate epilogue ------------------------
__device__ __forceinline__ float warp_sum(float v) {
#pragma unroll
    for (int o = 16; o; o >>= 1) v += __shfl_down_sync(0xffffffffu, v, o);
    return v;
}
__device__ __forceinline__ float sigmoidf_(float x) { return 1.0f / (1.0f + expf(-x)); }

__global__ __launch_bounds__(256)
void lstm_epilogue(const float* __restrict__ cx,
                   const float* __restrict__ w1, const float* __restrict__ b1,
                   const float* __restrict__ w2, const float* __restrict__ b2,
                   const float* __restrict__ w3, const float* __restrict__ b3,
                   float* __restrict__ hx_new,
                   float* __restrict__ cx_new)
{
    const int r   = blockIdx.x;
    const int tid = threadIdx.x;
    const int lane = tid & 31;
    const int wrp  = tid >> 5;

    const float4* __restrict__ ri4 =
        reinterpret_cast<const float4*>(g_i2h + (size_t)r * FH_DIM);
    const float4* __restrict__ rh4 =
        reinterpret_cast<const float4*>(g_h2h + (size_t)r * FH_DIM);

    __shared__ float s_i[FH_DIM];
    __shared__ float s_h[FH_DIM];
    __shared__ float sc[4][8];
    float4* s_i4 = reinterpret_cast<float4*>(s_i);
    float4* s_h4 = reinterpret_cast<float4*>(s_h);

    float s1 = 0.f, q1 = 0.f, s2 = 0.f, q2 = 0.f;
#pragma unroll
    for (int u = 0; u < 4; u++) {
        int j = tid + u * 256;                 // float4 index 0..1023
        float4 a = ri4[j], b = rh4[j];
        s_i4[j] = a; s_h4[j] = b;
        s1 += a.x + a.y + a.z + a.w;
        q1 += a.x * a.x + a.y * a.y + a.z * a.z + a.w * a.w;
        s2 += b.x + b.y + b.z + b.w;
        q2 += b.x * b.x + b.y * b.y + b.z * b.z + b.w * b.w;
    }
    s1 = warp_sum(s1); q1 = warp_sum(q1);
    s2 = warp_sum(s2); q2 = warp_sum(q2);
    if (lane == 0) { sc[0][wrp] = s1; sc[1][wrp] = q1; sc[2][wrp] = s2; sc[3][wrp] = q2; }
    __syncthreads();
    if (tid == 0) {
        float t0 = 0, t1 = 0, t2 = 0, t3 = 0;
#pragma unroll
        for (int i = 0; i < 8; i++) { t0 += sc[0][i]; t1 += sc[1][i]; t2 += sc[2][i]; t3 += sc[3][i]; }
        sc[0][0] = t0; sc[1][0] = t1; sc[2][0] = t2; sc[3][0] = t3;
    }
    __syncthreads();
    s1 = sc[0][0]; q1 = sc[1][0]; s2 = sc[2][0]; q2 = sc[3][0];

    const float inv_n = 1.0f / (float)FH_DIM;
    const float m1 = s1 * inv_n;
    const float m2 = s2 * inv_n;
    float var1 = fmaxf((q1 - s1 * m1) / (float)(FH_DIM - 1), 0.f);
    float var2 = fmaxf((q2 - s2 * m2) / (float)(FH_DIM - 1), 0.f);
    const float d1 = 1.0f / (sqrtf(var1) + LN_EPS);
    const float d2 = 1.0f / (sqrtf(var2) + LN_EPS);

    float c_reg[4], o_reg[4];
    float s3 = 0.f, q3 = 0.f;
#pragma unroll
    for (int u = 0; u < 4; u++) {
        const int h = tid + u * 256;

        float xi = fmaf((s_i[h] - m1) * d1, w1[h], b1[h])
                 + fmaf((s_h[h] - m2) * d2, w2[h], b2[h]);
        int jf = h + H_DIM;
        float xf = fmaf((s_i[jf] - m1) * d1, w1[jf], b1[jf])
                 + fmaf((s_h[jf] - m2) * d2, w2[jf], b2[jf]);
        int jo = h + 2 * H_DIM;
        float xo = fmaf((s_i[jo] - m1) * d1, w1[jo], b1[jo])
                 + fmaf((s_h[jo] - m2) * d2, w2[jo], b2[jo]);
        int jc = h + 3 * H_DIM;
        float xc = fmaf((s_i[jc] - m1) * d1, w1[jc], b1[jc])
                 + fmaf((s_h[jc] - m2) * d2, w2[jc], b2[jc]);

        float ig = sigmoidf_(xi);
        float fg = sigmoidf_(xf + FGBIAS);
        float og = sigmoidf_(xo);
        float ct = tanhf(xc);

        float c = fg * cx[(size_t)r * H_DIM + h] + ig * ct;
        c_reg[u] = c;
        o_reg[u] = og;
        s3 += c; q3 += c * c;
        cx_new[(size_t)r * H_DIM + h] = c;
    }

    __syncthreads();
    s3 = warp_sum(s3); q3 = warp_sum(q3);
    if (lane == 0) { sc[0][wrp] = s3; sc[1][wrp] = q3; }
    __syncthreads();
    if (tid == 0) {
        float t0 = 0, t1 = 0;
#pragma unroll
        for (int i = 0; i < 8; i++) { t0 += sc[0][i]; t1 += sc[1][i]; }
        sc[0][0] = t0; sc[1][0] = t1;
    }
    __syncthreads();
    s3 = sc[0][0]; q3 = sc[1][0];

    const float m3 = s3 / (float)H_DIM;
    float var3 = fmaxf((q3 - s3 * m3) / (float)(H_DIM - 1), 0.f);
    const float d3 = 1.0f / (sqrtf(var3) + LN_EPS);

#pragma unroll
    for (int u = 0; u < 4; u++) {
        const int h = tid + u * 256;
        float ln = fmaf((c_reg[u] - m3) * d3, w3[h], b3[h]);
        hx_new[(size_t)r * H_DIM + h] = o_reg[u] * tanhf(ln);
    }
}

// ------------------------------- launcher ----------------------------------
extern "C" void kernel_launch(void* const* d_in, const int* in_sizes, int n_in,
                              void* d_out, int out_size)
{
    const float* inputs   = (const float*)d_in[0];
    const float* hx       = (const float*)d_in[1];
    const float* cx       = (const float*)d_in[2];
    const float* w_i2h    = (const float*)d_in[3];
    const float* b_i2h    = (const float*)d_in[4];
    const float* w_h2h    = (const float*)d_in[5];
    const float* b_h2h    = (const float*)d_in[6];
    const float* ln_i2h_w = (const float*)d_in[7];
    const float* ln_i2h_b = (const float*)d_in[8];
    const float* ln_h2h_w = (const float*)d_in[9];
    const float* ln_h2h_b = (const float*)d_in[10];
    const float* ln_h2o_w = (const float*)d_in[11];
    const float* ln_h2o_b = (const float*)d_in[12];

    float* out    = (float*)d_out;
    float* hx_new = out;
    float* cx_new = out + (size_t)B_DIM * H_DIM;

    static int smem_set = 0;
    if (!smem_set) {
        cudaFuncSetAttribute(gemm_tc, cudaFuncAttributeMaxDynamicSharedMemorySize, GEMM_SMEM);
        smem_set = 1;
    }

    convert_fp16<<<dim3(2048, 4), 256>>>(inputs, hx, w_i2h, w_h2h);

    gemm_tc<<<dim3(FH_DIM / 128, B_DIM / 128, 2), 256, GEMM_SMEM>>>(b_i2h, b_h2h);

    lstm_epilogue<<<B_DIM, 256>>>(cx,
                                  ln_i2h_w, ln_i2h_b,
                                  ln_h2h_w, ln_h2h_b,
                                  ln_h2o_w, ln_h2o_b,
                                  hx_new, cx_new);
}